// round 6
// baseline (speedup 1.0000x reference)
#include <cuda_runtime.h>

#define FULLMASK 0xffffffffu

constexpr int   B_     = 256;
constexpr int   T_     = 256;
constexpr int   C_     = 1024;
constexpr int   L_     = 32;
constexpr int   S_     = 65;      // 2*L+1 extended states
constexpr int   SP_    = 34;      // compact row: [blank, lab0..lab31, pad]
constexpr int   BLANK_ = C_ - 1;
constexpr float PRE    = 512.0f;  // 2^9 per-step prescale
constexpr int   PRE_E  = 9;
constexpr float EPS    = 1e-7f;
constexpr float EPS_S  = EPS * PRE;

// compact gathered probs, 8.9 MB (L2-resident between the two kernels)
__device__ float g_scr[(size_t)B_ * T_ * SP_];

__device__ __forceinline__ int kidx(int s) {
    return (s >= S_) ? 33 : ((s & 1) ? ((s >> 1) + 1) : 0);
}
__device__ __forceinline__ float allow_fwd(int s, const int* labs) {
    if (!(s & 1) || s >= S_) return 0.0f;
    const int j = (s - 1) >> 1;
    return (j == 0 || labs[j] != labs[j - 1]) ? 1.0f : 0.0f;
}
__device__ __forceinline__ float allow_bwd(int s, const int* labs) {
    if (!(s & 1) || (s + 2) > S_ - 1) return 0.0f;
    const int jn = (s + 1) >> 1, jp = (s - 1) >> 1;
    return (labs[jn] != labs[jp]) ? 1.0f : 0.0f;
}
__device__ __forceinline__ int renorm(float& r0, float& r1, float& r2) {
    float m = fmaxf(fmaxf(r0, r1), r2);
#pragma unroll
    for (int o = 16; o; o >>= 1)
        m = fmaxf(m, __shfl_xor_sync(FULLMASK, m, o));
    const int e = (__float_as_int(m) >> 23) - 127;
    const float sc = __int_as_float((127 - e) << 23);  // exact 2^-e
    r0 *= sc; r1 *= sc; r2 *= sc;
    return e;
}
__device__ __forceinline__ float ldg_cg(const float* p) {
    float v;
    asm volatile("ld.global.cg.f32 %0, [%1];" : "=f"(v) : "l"(p));
    return v;
}

// ---------------------------------------------------------------------------
// Kernel 1: saturating gather. CTA = (batch, 32-row chunk). 2048 CTAs x 256.
// Each thread issues 5 independent LDGs into registers, then 5 stores.
// ---------------------------------------------------------------------------
__global__ __launch_bounds__(256)
void ctc_gather_kernel(const int* __restrict__ y_true,
                       const float* __restrict__ y_pred)
{
    __shared__ int labsx[33];   // [blank, lab0..lab31]

    const int bid   = blockIdx.x;
    const int b     = bid >> 3;
    const int chunk = (bid & 7) << 5;          // row base within batch
    const int tid   = threadIdx.x;

    if (tid < 33)
        labsx[tid] = tid ? __ldg(y_true + b * L_ + tid - 1) : BLANK_;
    __syncthreads();

    const float* base = y_pred + ((size_t)b * T_ + chunk) * C_;

    // 32 rows x 33 items = 1056 items, 5 strided items per thread
    float v[5];
    int   rr[5], cc[5];
#pragma unroll
    for (int i = 0; i < 5; ++i) {
        const int f = tid + i * 256;
        if (f < 1056) {
            const int row = f / 33;
            const int c   = f - 33 * row;
            rr[i] = row; cc[i] = c;
            v[i]  = ldg_cg(base + (size_t)row * C_ + labsx[c]);
        }
    }
    float* orow = g_scr + ((size_t)b * T_ + chunk) * SP_;
#pragma unroll
    for (int i = 0; i < 5; ++i) {
        const int f = tid + i * 256;
        if (f < 1056)
            orow[rr[i] * SP_ + cc[i]] = fmaf(v[i], PRE, EPS_S);
    }
}

// ---------------------------------------------------------------------------
// Kernel 2: per-batch scan. Copy compact slab (L2-hot) to smem, then
// two-warp fwd/bwd recurrence meeting at t=127/128.
// ---------------------------------------------------------------------------
__global__ __launch_bounds__(256, 2)
void ctc_scan_kernel(const int* __restrict__ y_true,
                     float* __restrict__ out)
{
    __shared__ float slab[T_ * SP_];   // 34816 B
    __shared__ int   labs[L_];
    __shared__ float exA[66], exB[66];
    __shared__ int   exE[2];

    const int b    = blockIdx.x;
    const int tid  = threadIdx.x;
    const int lane = tid & 31;
    const int wid  = tid >> 5;

    if (tid < L_) labs[tid] = __ldg(y_true + b * L_ + tid);

    // coalesced float4 copy of this batch's compact slab (2176 float4s)
    {
        const float4* src = (const float4*)(g_scr + (size_t)b * T_ * SP_);
        float4*       dst = (float4*)slab;
        for (int i = tid; i < (T_ * SP_) / 4; i += 256)
            dst[i] = src[i];
    }
    // dummy-state pad (col 33 holds garbage from scratch)
    slab[tid * SP_ + 33] = 0.0f;
    __syncthreads();

    const int s0 = 3 * lane, s1 = s0 + 1, s2 = s0 + 2;
    const int k0 = kidx(s0), k1 = kidx(s1), k2 = kidx(s2);

    if (wid == 0) {
        // forward: alpha_0 .. alpha_127
        const float a0 = allow_fwd(s0, labs);
        const float a1 = allow_fwd(s1, labs);
        const float a2 = allow_fwd(s2, labs);

        float r0 = 0.0f, r1 = 0.0f, r2 = 0.0f;
        if (lane == 0) { r0 = slab[0]; r1 = slab[1]; }

        float pa[4], pb[4], pc[4];
#pragma unroll
        for (int j = 0; j < 4; ++j) {
            const float* sr = slab + (1 + j) * SP_;
            pa[j] = sr[k0]; pb[j] = sr[k1]; pc[j] = sr[k2];
        }

        int Eacc = 0;
        for (int tb = 1; tb < 128; tb += 4) {
#pragma unroll
            for (int j = 0; j < 4; ++j) {
                const int t = tb + j;
                if (t < 128) {
                    const float p0 = pa[j], p1 = pb[j], p2 = pc[j];
                    const int tp = t + 4;
                    if (tp < 128) {
                        const float* sr = slab + tp * SP_;
                        pa[j] = sr[k0]; pb[j] = sr[k1]; pc[j] = sr[k2];
                    }
                    float u1 = __shfl_up_sync(FULLMASK, r1, 1);
                    float u2 = __shfl_up_sync(FULLMASK, r2, 1);
                    if (lane == 0) { u1 = 0.0f; u2 = 0.0f; }
                    const float n0 = p0 * fmaf(a0, u1, r0 + u2);
                    const float n1 = p1 * fmaf(a1, u2, r1 + r0);
                    const float n2 = p2 * fmaf(a2, r0, r2 + r1);
                    r0 = n0; r1 = n1; r2 = n2;
                    if ((t & 7) == 0) Eacc += renorm(r0, r1, r2);
                }
            }
        }
        if (lane < 22) { exA[s0] = r0; exA[s1] = r1; exA[s2] = r2; }
        if (lane == 0) exE[0] = Eacc;
    }
    else if (wid == 1) {
        // backward: c_t = p_t * beta_t for t = 255 .. 128, then beta_127
        const int lab = labs[lane];
        const unsigned nzm = __ballot_sync(FULLMASK, lab != 0);
        const int len = __popc(nzm);
        int ilb = 2 * len;
        int ill = 2 * len - 1;
        if (ill < 0) ill += S_;

        const float a0 = allow_bwd(s0, labs);
        const float a1 = allow_bwd(s1, labs);
        const float a2 = allow_bwd(s2, labs);

        float r0, r1, r2;
        {
            const float* sr = slab + 255 * SP_;
            r0 = (s0 == ilb || s0 == ill) ? sr[k0] : 0.0f;
            r1 = (s1 == ilb || s1 == ill) ? sr[k1] : 0.0f;
            r2 = (s2 == ilb || s2 == ill) ? sr[k2] : 0.0f;
        }

        float pa[4], pb[4], pc[4];
#pragma unroll
        for (int j = 0; j < 4; ++j) {
            const float* sr = slab + (254 - j) * SP_;
            pa[j] = sr[k0]; pb[j] = sr[k1]; pc[j] = sr[k2];
        }

        int Eacc = 0;
        for (int tb = 254; tb >= 128; tb -= 4) {
#pragma unroll
            for (int j = 0; j < 4; ++j) {
                const int t = tb - j;
                if (t >= 128) {
                    const float p0 = pa[j], p1 = pb[j], p2 = pc[j];
                    const int tm = t - 4;
                    if (tm >= 128) {
                        const float* sr = slab + tm * SP_;
                        pa[j] = sr[k0]; pb[j] = sr[k1]; pc[j] = sr[k2];
                    }
                    const float u0 = __shfl_down_sync(FULLMASK, r0, 1);
                    const float u1 = __shfl_down_sync(FULLMASK, r1, 1);
                    const float B0 = fmaf(a0, r2, r0 + r1);
                    const float B1 = fmaf(a1, u0, r1 + r2);
                    const float B2 = fmaf(a2, u1, r2 + u0);
                    r0 = p0 * B0; r1 = p1 * B1; r2 = p2 * B2;
                    if ((t & 7) == 0) Eacc += renorm(r0, r1, r2);
                }
            }
        }
        // beta_127 combine (no p multiply) from c_128
        const float u0 = __shfl_down_sync(FULLMASK, r0, 1);
        const float u1 = __shfl_down_sync(FULLMASK, r1, 1);
        const float B0 = fmaf(a0, r2, r0 + r1);
        const float B1 = fmaf(a1, u0, r1 + r2);
        const float B2 = fmaf(a2, u1, r2 + u0);
        if (lane < 22) { exB[s0] = B0; exB[s1] = B1; exB[s2] = B2; }
        if (lane == 0) exE[1] = Eacc;
    }
    __syncthreads();

    // combine: P = sum_s alpha_127[s] * beta_127[s]
    if (wid == 0) {
        float part = 0.0f;
        if (lane < 22)
            part = exA[s0] * exB[s0] + exA[s1] * exB[s1] + exA[s2] * exB[s2];
#pragma unroll
        for (int o = 16; o; o >>= 1)
            part += __shfl_xor_sync(FULLMASK, part, o);
        if (lane == 0) {
            const float LN2 = 0.6931471805599453f;
            out[b] = -(logf(part) +
                       (float)(exE[0] + exE[1] - PRE_E * T_) * LN2);
        }
    }
}

extern "C" void kernel_launch(void* const* d_in, const int* in_sizes, int n_in,
                              void* d_out, int out_size)
{
    (void)n_in; (void)out_size;
    const int*   y_true;
    const float* y_pred;
    if (in_sizes[0] == B_ * L_) {
        y_true = (const int*)d_in[0];
        y_pred = (const float*)d_in[1];
    } else {
        y_true = (const int*)d_in[1];
        y_pred = (const float*)d_in[0];
    }
    ctc_gather_kernel<<<B_ * 8, 256>>>(y_true, y_pred);
    ctc_scan_kernel<<<B_, 256>>>(y_true, (float*)d_out);
}

// round 7
// speedup vs baseline: 1.1860x; 1.1860x over previous
#include <cuda_runtime.h>

#define FULLMASK 0xffffffffu

constexpr int   B_     = 256;
constexpr int   T_     = 256;
constexpr int   C_     = 1024;
constexpr int   L_     = 32;
constexpr int   S_     = 65;      // 2*L+1 extended states
constexpr int   SP_    = 34;      // compact row: [blank, lab0..lab31, pad]
constexpr int   BLANK_ = C_ - 1;
constexpr float PRE    = 512.0f;  // 2^9 per-step prescale
constexpr int   PRE_E  = 9;
constexpr float EPS    = 1e-7f;
constexpr float EPS_S  = EPS * PRE;

// compact gathered probs, 8.9 MB (L2-resident between the two kernels)
__device__ float g_scr[(size_t)B_ * T_ * SP_];

__device__ __forceinline__ int kidx(int s) {
    return (s >= S_) ? 33 : ((s & 1) ? ((s >> 1) + 1) : 0);
}
__device__ __forceinline__ float allow_fwd(int s, const int* labs) {
    if (!(s & 1) || s >= S_) return 0.0f;
    const int j = (s - 1) >> 1;
    return (j == 0 || labs[j] != labs[j - 1]) ? 1.0f : 0.0f;
}
__device__ __forceinline__ float allow_bwd(int s, const int* labs) {
    if (!(s & 1) || (s + 2) > S_ - 1) return 0.0f;
    const int jn = (s + 1) >> 1, jp = (s - 1) >> 1;
    return (labs[jn] != labs[jp]) ? 1.0f : 0.0f;
}

// exact power-of-2 warp renorm using redux (values are all >= 0)
__device__ __forceinline__ int renorm(float& r0, float& r1, float& r2) {
    float m = fmaxf(fmaxf(r0, r1), r2);
    int im = __float_as_int(m);
    asm volatile("redux.sync.max.s32 %0, %1, 0xffffffff;" : "=r"(im) : "r"(im));
    const int e = (im >> 23) - 127;
    const float sc = __int_as_float((127 - e) << 23);  // exact 2^-e
    r0 *= sc; r1 *= sc; r2 *= sc;
    return e;
}
__device__ __forceinline__ float ldg_cg(const float* p) {
    float v;
    asm volatile("ld.global.cg.f32 %0, [%1];" : "=f"(v) : "l"(p));
    return v;
}

// ---------------------------------------------------------------------------
// Kernel 1: saturating gather (unchanged from R6; ~31 us, near random-access
// DRAM ceiling). CTA = (batch, 32-row chunk). 2048 CTAs x 256 threads.
// ---------------------------------------------------------------------------
__global__ __launch_bounds__(256)
void ctc_gather_kernel(const int* __restrict__ y_true,
                       const float* __restrict__ y_pred)
{
    __shared__ int labsx[33];   // [blank, lab0..lab31]

    const int bid   = blockIdx.x;
    const int b     = bid >> 3;
    const int chunk = (bid & 7) << 5;
    const int tid   = threadIdx.x;

    if (tid < 33)
        labsx[tid] = tid ? __ldg(y_true + b * L_ + tid - 1) : BLANK_;
    __syncthreads();

    const float* base = y_pred + ((size_t)b * T_ + chunk) * C_;

    float v[5];
    int   rr[5], cc[5];
#pragma unroll
    for (int i = 0; i < 5; ++i) {
        const int f = tid + i * 256;
        if (f < 1056) {
            const int row = f / 33;
            const int c   = f - 33 * row;
            rr[i] = row; cc[i] = c;
            v[i]  = ldg_cg(base + (size_t)row * C_ + labsx[c]);
        }
    }
    float* orow = g_scr + ((size_t)b * T_ + chunk) * SP_;
#pragma unroll
    for (int i = 0; i < 5; ++i) {
        const int f = tid + i * 256;
        if (f < 1056)
            orow[rr[i] * SP_ + cc[i]] = fmaf(v[i], PRE, EPS_S);
    }
}

// ---------------------------------------------------------------------------
// Kernel 2: per-batch scan, branch-free inner loop.
// ---------------------------------------------------------------------------
__global__ __launch_bounds__(256)
void ctc_scan_kernel(const int* __restrict__ y_true,
                     float* __restrict__ out)
{
    __shared__ float slab[T_ * SP_];   // 34816 B
    __shared__ int   labs[L_];
    __shared__ float exA[66], exB[66];
    __shared__ int   exE[2];

    const int b    = blockIdx.x;
    const int tid  = threadIdx.x;
    const int lane = tid & 31;
    const int wid  = tid >> 5;

    if (tid < L_) labs[tid] = __ldg(y_true + b * L_ + tid);

    // coalesced float4 copy of this batch's compact slab (L2-hot)
    {
        const float4* src = (const float4*)(g_scr + (size_t)b * T_ * SP_);
        float4*       dst = (float4*)slab;
        for (int i = tid; i < (T_ * SP_) / 4; i += 256)
            dst[i] = src[i];
    }
    slab[tid * SP_ + 33] = 0.0f;   // dummy-state pad column
    __syncthreads();

    const int s0 = 3 * lane, s1 = s0 + 1, s2 = s0 + 2;
    const int k0 = kidx(s0), k1 = kidx(s1), k2 = kidx(s2);

    if (wid == 0) {
        // ---------------- forward: alpha_0 .. alpha_127 ----------------
        const float a0 = allow_fwd(s0, labs);
        const float a1 = allow_fwd(s1, labs);
        const float a2 = allow_fwd(s2, labs);

        float r0 = 0.0f, r1 = 0.0f, r2 = 0.0f;
        if (lane == 0) { r0 = slab[0]; r1 = slab[1]; }

        int E = 0;

#define FSTEP(tt) {                                                  \
            const float* sr = slab + (tt) * SP_;                     \
            const float p0 = sr[k0], p1 = sr[k1], p2 = sr[k2];       \
            float u1 = __shfl_up_sync(FULLMASK, r1, 1);              \
            float u2 = __shfl_up_sync(FULLMASK, r2, 1);              \
            u1 = lane ? u1 : 0.0f;                                   \
            u2 = lane ? u2 : 0.0f;                                   \
            const float n0 = p0 * fmaf(a0, u1, r0 + u2);             \
            const float n1 = p1 * fmaf(a1, u2, r1 + r0);             \
            const float n2 = p2 * fmaf(a2, r0, r2 + r1);             \
            r0 = n0; r1 = n1; r2 = n2; }

        int t = 1;
        for (int blk = 0; blk < 15; ++blk) {      // 15 x 8 = 120 steps
#pragma unroll
            for (int j = 0; j < 8; ++j) FSTEP(t + j);
            E += renorm(r0, r1, r2);
            t += 8;
        }
#pragma unroll
        for (int j = 0; j < 7; ++j) FSTEP(t + j);  // tail t = 121..127
        E += renorm(r0, r1, r2);
#undef FSTEP

        if (lane < 22) { exA[s0] = r0; exA[s1] = r1; exA[s2] = r2; }
        if (lane == 0) exE[0] = E;
    }
    else if (wid == 1) {
        // ---------------- backward: c_t = p_t * beta_t, t = 255..128 ----
        const int lab = labs[lane];
        const unsigned nzm = __ballot_sync(FULLMASK, lab != 0);
        const int len = __popc(nzm);
        int ilb = 2 * len;
        int ill = 2 * len - 1;
        if (ill < 0) ill += S_;

        const float a0 = allow_bwd(s0, labs);
        const float a1 = allow_bwd(s1, labs);
        const float a2 = allow_bwd(s2, labs);

        float r0, r1, r2;
        {
            const float* sr = slab + 255 * SP_;
            r0 = (s0 == ilb || s0 == ill) ? sr[k0] : 0.0f;
            r1 = (s1 == ilb || s1 == ill) ? sr[k1] : 0.0f;
            r2 = (s2 == ilb || s2 == ill) ? sr[k2] : 0.0f;
        }

        int E = 0;

#define BSTEP(tt) {                                                  \
            const float* sr = slab + (tt) * SP_;                     \
            const float p0 = sr[k0], p1 = sr[k1], p2 = sr[k2];       \
            const float u0 = __shfl_down_sync(FULLMASK, r0, 1);      \
            const float u1 = __shfl_down_sync(FULLMASK, r1, 1);      \
            const float B0 = fmaf(a0, r2, r0 + r1);                  \
            const float B1 = fmaf(a1, u0, r1 + r2);                  \
            const float B2 = fmaf(a2, u1, r2 + u0);                  \
            r0 = p0 * B0; r1 = p1 * B1; r2 = p2 * B2; }

        int t = 254;
        for (int blk = 0; blk < 15; ++blk) {      // t = 254..135
#pragma unroll
            for (int j = 0; j < 8; ++j) BSTEP(t - j);
            E += renorm(r0, r1, r2);
            t -= 8;
        }
#pragma unroll
        for (int j = 0; j < 7; ++j) BSTEP(t - j);  // tail t = 134..128
        E += renorm(r0, r1, r2);
#undef BSTEP

        // beta_127 combine (no p multiply) from c_128
        const float u0 = __shfl_down_sync(FULLMASK, r0, 1);
        const float u1 = __shfl_down_sync(FULLMASK, r1, 1);
        const float B0 = fmaf(a0, r2, r0 + r1);
        const float B1 = fmaf(a1, u0, r1 + r2);
        const float B2 = fmaf(a2, u1, r2 + u0);
        if (lane < 22) { exB[s0] = B0; exB[s1] = B1; exB[s2] = B2; }
        if (lane == 0) exE[1] = E;
    }
    __syncthreads();

    // combine: P = sum_s alpha_127[s] * beta_127[s]
    if (wid == 0) {
        float part = 0.0f;
        if (lane < 22)
            part = exA[s0] * exB[s0] + exA[s1] * exB[s1] + exA[s2] * exB[s2];
#pragma unroll
        for (int o = 16; o; o >>= 1)
            part += __shfl_xor_sync(FULLMASK, part, o);
        if (lane == 0) {
            const float LN2 = 0.6931471805599453f;
            out[b] = -(logf(part) +
                       (float)(exE[0] + exE[1] - PRE_E * T_) * LN2);
        }
    }
}

extern "C" void kernel_launch(void* const* d_in, const int* in_sizes, int n_in,
                              void* d_out, int out_size)
{
    (void)n_in; (void)out_size;
    const int*   y_true;
    const float* y_pred;
    if (in_sizes[0] == B_ * L_) {
        y_true = (const int*)d_in[0];
        y_pred = (const float*)d_in[1];
    } else {
        y_true = (const int*)d_in[1];
        y_pred = (const float*)d_in[0];
    }
    ctc_gather_kernel<<<B_ * 8, 256>>>(y_true, y_pred);
    ctc_scan_kernel<<<B_, 256>>>(y_true, (float*)d_out);
}